// round 3
// baseline (speedup 1.0000x reference)
#include <cuda_runtime.h>
#include <cstdint>

#define D 64
#define NODE_STRIDE 256        // 4 layers * 64 floats, node-major [n][4][64]
#define MAX_NODES   150016
#define MAX_EDGES   3000000
#define SCAN_BS     512

// ---------------------------------------------------------------------------
// Static scratch (allocation-free rule: __device__ globals)
// ---------------------------------------------------------------------------
__device__ int  d_cnt[MAX_NODES];
__device__ int  d_row_ptr[MAX_NODES + 1];
__device__ int  d_cursor[MAX_NODES];
__device__ int  d_bsums[SCAN_BS];
__device__ int2 d_edges_sorted[MAX_EDGES];   // (col, val bits), grouped by row

// ---------------------------------------------------------------------------
// CSR build
// ---------------------------------------------------------------------------
__global__ void lgcn_zero_cnt(int n) {
    int i = blockIdx.x * blockDim.x + threadIdx.x;
    if (i < n) d_cnt[i] = 0;
}

__global__ void lgcn_hist(const int* __restrict__ edge_row, int n_edges) {
    int e = blockIdx.x * blockDim.x + threadIdx.x;
    if (e < n_edges) atomicAdd(&d_cnt[edge_row[e]], 1);
}

__global__ void lgcn_scan_blocks(int n) {
    __shared__ int s[SCAN_BS];
    int t = threadIdx.x;
    int i = blockIdx.x * SCAN_BS + t;
    int v = (i < n) ? d_cnt[i] : 0;
    s[t] = v;
    __syncthreads();
    #pragma unroll
    for (int off = 1; off < SCAN_BS; off <<= 1) {
        int tmp = (t >= off) ? s[t - off] : 0;
        __syncthreads();
        s[t] += tmp;
        __syncthreads();
    }
    if (i < n) d_row_ptr[i] = s[t] - v;      // exclusive
    if (t == SCAN_BS - 1) d_bsums[blockIdx.x] = s[t];
}

__global__ void lgcn_scan_sums(int nb) {
    __shared__ int s[SCAN_BS];
    int t = threadIdx.x;
    int v = (t < nb) ? d_bsums[t] : 0;
    s[t] = v;
    __syncthreads();
    #pragma unroll
    for (int off = 1; off < SCAN_BS; off <<= 1) {
        int tmp = (t >= off) ? s[t - off] : 0;
        __syncthreads();
        s[t] += tmp;
        __syncthreads();
    }
    if (t < nb) d_bsums[t] = s[t] - v;       // exclusive
}

__global__ void lgcn_scan_add(int n, int n_edges) {
    int i = blockIdx.x * blockDim.x + threadIdx.x;
    if (i < n) {
        int p = d_row_ptr[i] + d_bsums[i / SCAN_BS];
        d_row_ptr[i] = p;
        d_cursor[i]  = p;
    }
    if (i == 0) d_row_ptr[n] = n_edges;
}

__global__ void lgcn_scatter(const int*   __restrict__ edge_row,
                             const int*   __restrict__ edge_col,
                             const float* __restrict__ edge_val,
                             int n_edges) {
    int e = blockIdx.x * blockDim.x + threadIdx.x;
    if (e >= n_edges) return;
    int r = edge_row[e];
    int p = atomicAdd(&d_cursor[r], 1);
    d_edges_sorted[p] = make_int2(edge_col[e], __float_as_int(edge_val[e]));
}

// ---------------------------------------------------------------------------
// embs[:,0,:] = concat(user_emb, item_emb)
// ---------------------------------------------------------------------------
__global__ void lgcn_init_kernel(const float* __restrict__ user_emb,
                                 const float* __restrict__ item_emb,
                                 float* __restrict__ embs,
                                 int n_users, int n) {
    int idx = blockIdx.x * blockDim.x + threadIdx.x;
    int total = n * (D / 4);
    if (idx >= total) return;
    int node = idx >> 4;
    int q    = idx & 15;
    const float4* src = (node < n_users)
        ? reinterpret_cast<const float4*>(user_emb + (size_t)node * D)
        : reinterpret_cast<const float4*>(item_emb + (size_t)(node - n_users) * D);
    reinterpret_cast<float4*>(embs + (size_t)node * NODE_STRIDE)[q] = src[q];
}

// ---------------------------------------------------------------------------
// SpMM, CSR, warp-per-row, half-warp-per-edge, float4 lanes, unroll-2.
// 4 independent 16B gathers in flight per warp per iteration.
// ---------------------------------------------------------------------------
__global__ void __launch_bounds__(512)
lgcn_spmm_csr(const float* __restrict__ x_base,  // embs + (l-1)*64
              float*       __restrict__ y_base,  // embs + l*64
              int n) {
    int warp = (blockIdx.x * blockDim.x + threadIdx.x) >> 5;
    if (warp >= n) return;
    int lane = threadIdx.x & 31;
    int half = lane >> 4;          // 0 or 1: which edge of the pair
    int hl   = lane & 15;          // float4 slot within the 256B row

    int start = d_row_ptr[warp];
    int deg   = d_row_ptr[warp + 1] - start;

    float4 acc0 = make_float4(0.f, 0.f, 0.f, 0.f);
    float4 acc1 = make_float4(0.f, 0.f, 0.f, 0.f);

    // each iteration: edges base+half (acc0) and base+2+half (acc1)
    for (int base = 0; base < deg; base += 4) {
        int e0 = base + half;
        int e1 = base + 2 + half;
        bool p0 = e0 < deg;
        bool p1 = e1 < deg;

        int2 m0 = p0 ? __ldg(&d_edges_sorted[start + e0]) : make_int2(0, 0);
        int2 m1 = p1 ? __ldg(&d_edges_sorted[start + e1]) : make_int2(0, 0);

        if (p0) {
            float w = __int_as_float(m0.y);
            float4 v = __ldg(&reinterpret_cast<const float4*>(
                                 x_base + (size_t)m0.x * NODE_STRIDE)[hl]);
            acc0.x += w * v.x;  acc0.y += w * v.y;
            acc0.z += w * v.z;  acc0.w += w * v.w;
        }
        if (p1) {
            float w = __int_as_float(m1.y);
            float4 v = __ldg(&reinterpret_cast<const float4*>(
                                 x_base + (size_t)m1.x * NODE_STRIDE)[hl]);
            acc1.x += w * v.x;  acc1.y += w * v.y;
            acc1.z += w * v.z;  acc1.w += w * v.w;
        }
    }

    acc0.x += acc1.x;  acc0.y += acc1.y;
    acc0.z += acc1.z;  acc0.w += acc1.w;

    // fold the two half-warps together (they hold the same hl slots)
    acc0.x += __shfl_down_sync(0xffffffffu, acc0.x, 16);
    acc0.y += __shfl_down_sync(0xffffffffu, acc0.y, 16);
    acc0.z += __shfl_down_sync(0xffffffffu, acc0.z, 16);
    acc0.w += __shfl_down_sync(0xffffffffu, acc0.w, 16);

    if (half == 0)
        reinterpret_cast<float4*>(y_base + (size_t)warp * NODE_STRIDE)[hl] = acc0;
}

// ---------------------------------------------------------------------------
// light_out = mean over layer axis; split into users/items.
// ---------------------------------------------------------------------------
__global__ void lgcn_mean_kernel(const float* __restrict__ embs,
                                 float* __restrict__ users,
                                 float* __restrict__ items,
                                 int n_users, int n) {
    int idx = blockIdx.x * blockDim.x + threadIdx.x;
    int total = n * (D / 4);
    if (idx >= total) return;
    int node = idx >> 4;
    int q    = idx & 15;

    const float4* base = reinterpret_cast<const float4*>(embs + (size_t)node * NODE_STRIDE);
    float4 a0 = base[q];
    float4 a1 = base[16 + q];
    float4 a2 = base[32 + q];
    float4 a3 = base[48 + q];

    float4 m = make_float4((a0.x + a1.x + a2.x + a3.x) * 0.25f,
                           (a0.y + a1.y + a2.y + a3.y) * 0.25f,
                           (a0.z + a1.z + a2.z + a3.z) * 0.25f,
                           (a0.w + a1.w + a2.w + a3.w) * 0.25f);

    float4* dst = (node < n_users)
        ? reinterpret_cast<float4*>(users + (size_t)node * D)
        : reinterpret_cast<float4*>(items + (size_t)(node - n_users) * D);
    dst[q] = m;
}

// ---------------------------------------------------------------------------
// out layout = [users (n_users*64)] [items (n_items*64)] [embs (n*4*64)]
// ---------------------------------------------------------------------------
extern "C" void kernel_launch(void* const* d_in, const int* in_sizes, int n_in,
                              void* d_out, int out_size) {
    const float* user_emb = (const float*)d_in[0];
    const float* item_emb = (const float*)d_in[1];
    const int*   edge_row = (const int*)d_in[2];
    const int*   edge_col = (const int*)d_in[3];
    const float* edge_val = (const float*)d_in[4];

    int n_users = in_sizes[0] / D;
    int n_items = in_sizes[1] / D;
    int n       = n_users + n_items;
    int n_edges = in_sizes[2];

    float* out   = (float*)d_out;
    float* users = out;
    float* items = out + (size_t)n_users * D;
    float* embs  = out + (size_t)n * D;   // [n][4][64]

    const int TPB = 256;
    int nb = (n + SCAN_BS - 1) / SCAN_BS;

    // --- CSR build ---
    lgcn_zero_cnt<<<(n + TPB - 1) / TPB, TPB>>>(n);
    lgcn_hist<<<(n_edges + TPB - 1) / TPB, TPB>>>(edge_row, n_edges);
    lgcn_scan_blocks<<<nb, SCAN_BS>>>(n);
    lgcn_scan_sums<<<1, SCAN_BS>>>(nb);
    lgcn_scan_add<<<(n + TPB - 1) / TPB, TPB>>>(n, n_edges);
    lgcn_scatter<<<(n_edges + TPB - 1) / TPB, TPB>>>(edge_row, edge_col, edge_val, n_edges);

    // --- layer 0 init ---
    {
        int total = n * (D / 4);
        lgcn_init_kernel<<<(total + TPB - 1) / TPB, TPB>>>(user_emb, item_emb, embs,
                                                           n_users, n);
    }

    // --- 3 SpMM layers (CSR gather-reduce, no atomics) ---
    {
        long long threads = (long long)n * 32;
        int grid = (int)((threads + 511) / 512);
        for (int l = 1; l <= 3; ++l) {
            lgcn_spmm_csr<<<grid, 512>>>(embs + (size_t)(l - 1) * D,
                                         embs + (size_t)l * D,
                                         n);
        }
    }

    // --- mean over layers ---
    {
        int total = n * (D / 4);
        lgcn_mean_kernel<<<(total + TPB - 1) / TPB, TPB>>>(embs, users, items,
                                                           n_users, n);
    }
}